// round 16
// baseline (speedup 1.0000x reference)
#include <cuda_runtime.h>
#include <cuda_bf16.h>
#include <cstdint>

// ---------------------------------------------------------------------------
// Problem constants
// ---------------------------------------------------------------------------
#define NVOC 10000
#define NIN  1024
#define NHID 256
#define G3   768
#define TT   128
#define BB   64
#define MM   (TT*BB)

#define CL 4                  // CTAs per cluster
#define LP 2                  // batch lanes per cluster
#define NCLUST (BB/LP)        // 32 clusters
#define SCAN_THREADS 384
#define LSTRIDE 264           // padded lane stride (floats)
#define HB (LP*LSTRIDE)

extern __shared__ char dsmem[];

// ---------------------------------------------------------------------------
// Device scratch
// ---------------------------------------------------------------------------
__device__ float g_xg1  [MM * G3];
__device__ float g_xg2  [MM * G3];
__device__ float g_hb2  [BB * G3];
__device__ float g_h1   [BB * NHID];
__device__ float g_preds[MM * NHID];
__device__ float g_WT1  [NHID * G3];
__device__ float g_WT2  [NHID * G3];
__device__ float g_Et  [NVOC * NIN];
__device__ float g_Wdt [NVOC * NHID];
__device__ float g_W1t [G3 * NIN];
__device__ float g_W2t [G3 * NIN];

// ---------------------------------------------------------------------------
// Helpers
// ---------------------------------------------------------------------------
__device__ __forceinline__ uint32_t smem_u32(const void* p) {
    uint32_t a;
    asm("{ .reg .u64 t; cvta.to.shared.u64 t, %1; cvt.u32.u64 %0, t; }"
        : "=r"(a) : "l"(p));
    return a;
}
__device__ __forceinline__ float to_tf32f(float x) {
    float y;
    asm("cvt.rna.tf32.f32 %0, %1;" : "=f"(y) : "f"(x));
    return y;
}
__device__ __forceinline__ unsigned long long f2pack(float lo, float hi) {
    unsigned long long v;
    asm("mov.b64 %0, {%1, %2};" : "=l"(v) : "f"(lo), "f"(hi));
    return v;
}
__device__ __forceinline__ void f2unpack(unsigned long long v, float& lo, float& hi) {
    asm("mov.b64 {%0, %1}, %2;" : "=f"(lo), "=f"(hi) : "l"(v));
}
__device__ __forceinline__ void ffma2(unsigned long long& d, unsigned long long a,
                                      unsigned long long b) {
    asm("fma.rn.f32x2 %0, %1, %2, %3;" : "=l"(d) : "l"(a), "l"(b), "l"(d));
}
__device__ __forceinline__ void mma_tf32(float* d, uint32_t a0, uint32_t a1,
                                         uint32_t a2, uint32_t a3,
                                         uint32_t b0, uint32_t b1) {
    asm volatile(
        "mma.sync.aligned.m16n8k8.row.col.f32.tf32.tf32.f32 "
        "{%0,%1,%2,%3}, {%4,%5,%6,%7}, {%8,%9}, {%0,%1,%2,%3};"
        : "+f"(d[0]), "+f"(d[1]), "+f"(d[2]), "+f"(d[3])
        : "r"(a0), "r"(a1), "r"(a2), "r"(a3), "r"(b0), "r"(b1));
}
__device__ __forceinline__ uint32_t my_ctarank() {
    uint32_t r;
    asm("mov.u32 %0, %%cluster_ctarank;" : "=r"(r));
    return r;
}
__device__ __forceinline__ uint32_t mapa_u32(uint32_t laddr, int p) {
    uint32_t ra;
    asm volatile("mapa.shared::cluster.u32 %0, %1, %2;"
                 : "=r"(ra) : "r"(laddr), "r"(p));
    return ra;
}
__device__ __forceinline__ void st_async_f32(uint32_t raddr, uint32_t rmbar,
                                             float v) {
    asm volatile(
        "st.async.shared::cluster.mbarrier::complete_tx::bytes.b32 [%0], %1, [%2];"
        :: "r"(raddr), "r"(__float_as_uint(v)), "r"(rmbar) : "memory");
}
__device__ __forceinline__ void cp_async16(uint32_t dst, const void* src) {
    asm volatile("cp.async.cg.shared.global [%0], [%1], 16;"
                 :: "r"(dst), "l"(src) : "memory");
}
#define CP_COMMIT() asm volatile("cp.async.commit_group;" ::: "memory")

#define MBAR_INIT(a, n) \
    asm volatile("mbarrier.init.shared.b64 [%0], %1;" :: "r"(a), "r"(n) : "memory")
#define MBAR_EXPECT(a, tx) \
    asm volatile("mbarrier.arrive.expect_tx.shared.b64 _, [%0], %1;" \
                 :: "r"(a), "r"(tx) : "memory")
#define MBAR_WAIT_CL(a, ph) do {                                                \
    uint32_t _m = (a), _p = (ph), _d;                                           \
    asm volatile("{ .reg .pred p; "                                             \
        "mbarrier.try_wait.parity.acquire.cluster.shared::cta.b64 p, [%1], %2;" \
        " selp.b32 %0, 1, 0, p; }" : "=r"(_d) : "r"(_m), "r"(_p) : "memory");   \
    if (!_d) {                                                                  \
        asm volatile("{ .reg .pred P1; WL%=:"                                   \
            " mbarrier.try_wait.parity.acquire.cluster.shared::cta.b64 P1, [%0], %1, 0x989680;" \
            " @P1 bra.uni WD%=; bra.uni WL%=; WD%=: }"                          \
            :: "r"(_m), "r"(_p) : "memory");                                    \
    } } while (0)

// ---------------------------------------------------------------------------
// Fused tf32 pre-rounding prepass
// ---------------------------------------------------------------------------
#define NE4  (NVOC * NIN / 4)
#define NWD4 (NVOC * NHID / 4)
#define NW14 (G3 * NIN / 4)
#define NW24 (G3 * NIN / 4)

__global__ void prepass_all(const float* __restrict__ E,  float* __restrict__ Et,
                            const float* __restrict__ Wd, float* __restrict__ Wdt,
                            const float* __restrict__ W1, float* __restrict__ W1t,
                            const float* __restrict__ W2, float* __restrict__ W2t)
{
    const int total = NE4 + NWD4 + NW14 + NW24;
    for (int i = blockIdx.x * blockDim.x + threadIdx.x; i < total;
         i += gridDim.x * blockDim.x) {
        const float4* src;
        float4* dst;
        if (i < NE4) {
            src = (const float4*)E + i;
            dst = (float4*)Et + i;
        } else if (i < NE4 + NWD4) {
            int j = i - NE4;
            src = (const float4*)Wd + j;
            dst = (float4*)Wdt + j;
        } else if (i < NE4 + NWD4 + NW14) {
            int j = i - NE4 - NWD4;
            src = (const float4*)W1 + j;
            dst = (float4*)W1t + j;
        } else {
            int j = i - NE4 - NWD4 - NW14;
            int r = j / (NIN / 4), c = j - r * (NIN / 4);
            src = (const float4*)(W2 + (size_t)r * (NHID + NIN) + c * 4);
            dst = (float4*)(W2t + (size_t)r * NIN + c * 4);
        }
        float4 v = *src;
        v.x = to_tf32f(v.x); v.y = to_tf32f(v.y);
        v.z = to_tf32f(v.z); v.w = to_tf32f(v.w);
        *dst = v;
    }
}

// ---------------------------------------------------------------------------
__global__ void transpose_k2(const float* __restrict__ in0, float* __restrict__ out0,
                             const float* __restrict__ in1, float* __restrict__ out1)
{
    __shared__ float tile[32][33];
    const float* in  = blockIdx.z ? in1  : in0;
    float*       out = blockIdx.z ? out1 : out0;
    int r0 = blockIdx.x * 32;
    int c0 = blockIdx.y * 32;
    for (int i = threadIdx.y; i < 32; i += 8)
        tile[i][threadIdx.x] = in[(r0 + i) * NHID + (c0 + threadIdx.x)];
    __syncthreads();
    for (int i = threadIdx.y; i < 32; i += 8)
        out[(c0 + i) * G3 + (r0 + threadIdx.x)] = tile[threadIdx.x][i];
}

// ---------------------------------------------------------------------------
// tf32 mma.sync GEMM body (operands pre-rounded).
// ---------------------------------------------------------------------------
#define GM_THREADS 256
#define GNST 3
#define GM_SMEM (GNST * 32768)

template<int NST>
__device__ __forceinline__ void
gemm_body(const float* __restrict__ A, int lda,
          const float* __restrict__ Bw, int ldb,
          const float* __restrict__ bias,
          float* __restrict__ C, int ldc,
          const int* __restrict__ tok,
          int M, int N, int K, int bx, int by)
{
    float* smem = (float*)dsmem;
    const uint32_t sbase = smem_u32(dsmem);

    const int tid  = threadIdx.x;
    const int wid  = tid >> 5, lane = tid & 31;
    const int wm   = wid >> 1;
    const int wn   = wid & 1;
    const int gid  = lane >> 2;
    const int tig  = lane & 3;
    const int row0 = by * 128, col0 = bx * 128;

    const int sr = tid >> 3;
    const int sc = (tid & 7) * 4;
    const float* Aptr[4];
    const float* Bptr[4];
#pragma unroll
    for (int ps = 0; ps < 4; ps++) {
        int ar = row0 + sr + ps * 32;
        if (ar >= M) ar = M - 1;
        if (tok) ar = tok[ar];
        Aptr[ps] = A + (size_t)ar * lda + sc;
        int br = col0 + sr + ps * 32;
        if (br >= N) br = N - 1;
        Bptr[ps] = Bw + (size_t)br * ldb + sc;
    }
    uint32_t stOff[4];
#pragma unroll
    for (int ps = 0; ps < 4; ps++) {
        int r = sr + ps * 32;
        stOff[ps] = (r * 32 + 4 * ((sc >> 2) ^ (r & 7))) * 4;
    }

    const int NC = K >> 5;

    auto issue = [&](int idx) {
        uint32_t ab = sbase + (uint32_t)(idx % NST) * 32768u;
        const int co = idx * 32;
#pragma unroll
        for (int ps = 0; ps < 4; ps++) {
            cp_async16(ab + stOff[ps], Aptr[ps] + co);
            cp_async16(ab + 16384u + stOff[ps], Bptr[ps] + co);
        }
        CP_COMMIT();
    };

#pragma unroll
    for (int s = 0; s < NST - 1; s++) issue(s);

    float acc[2][8][4];
#pragma unroll
    for (int mt = 0; mt < 2; mt++)
#pragma unroll
        for (int nt = 0; nt < 8; nt++)
#pragma unroll
            for (int j = 0; j < 4; j++) acc[mt][nt][j] = 0.f;

    for (int i = 0; i < NC; i++) {
        asm volatile("cp.async.wait_group %0;" :: "n"(NST - 2) : "memory");
        __syncthreads();

        const uint32_t* Au = (const uint32_t*)(smem + (size_t)(i % NST) * 8192);
        const uint32_t* Bu = Au + 4096;

#pragma unroll
        for (int kk = 0; kk < 4; kk++) {
            const int s0 = 4 * (((kk * 2)    ) ^ gid);
            const int s1 = 4 * (((kk * 2) + 1) ^ gid);
            uint32_t af[2][4];
#pragma unroll
            for (int mt = 0; mt < 2; mt++) {
                int rA = wm * 32 + mt * 16 + gid;
                af[mt][0] = Au[rA * 32 + tig + s0];
                af[mt][1] = Au[(rA + 8) * 32 + tig + s0];
                af[mt][2] = Au[rA * 32 + tig + s1];
                af[mt][3] = Au[(rA + 8) * 32 + tig + s1];
            }
            uint32_t bf[8][2];
#pragma unroll
            for (int nt = 0; nt < 8; nt++) {
                int rB = wn * 64 + nt * 8 + gid;
                bf[nt][0] = Bu[rB * 32 + tig + s0];
                bf[nt][1] = Bu[rB * 32 + tig + s1];
            }
#pragma unroll
            for (int mt = 0; mt < 2; mt++)
#pragma unroll
                for (int nt = 0; nt < 8; nt++)
                    mma_tf32(acc[mt][nt], af[mt][0], af[mt][1], af[mt][2],
                             af[mt][3], bf[nt][0], bf[nt][1]);
        }

        if (i + NST - 1 < NC) issue(i + NST - 1);
        else                  CP_COMMIT();
    }

#pragma unroll
    for (int mt = 0; mt < 2; mt++) {
        int row = row0 + wm * 32 + mt * 16 + gid;
        if (row >= M) continue;
#pragma unroll
        for (int nt = 0; nt < 8; nt++) {
            int col = col0 + wn * 64 + nt * 8 + tig * 2;
            if (col >= N) continue;
            float b0v = bias ? bias[col] : 0.f;
            float* p0 = C + (size_t)row * ldc + col;
            float* p1 = C + (size_t)(row + 8) * ldc + col;
            if (col + 1 < N) {
                float b1v = bias ? bias[col + 1] : 0.f;
                *(float2*)p0 = make_float2(acc[mt][nt][0] + b0v,
                                           acc[mt][nt][1] + b1v);
                if (row + 8 < M)
                    *(float2*)p1 = make_float2(acc[mt][nt][2] + b0v,
                                               acc[mt][nt][3] + b1v);
            } else {
                p0[0] = acc[mt][nt][0] + b0v;
                if (row + 8 < M) p1[0] = acc[mt][nt][2] + b0v;
            }
        }
    }
}

__global__ void __launch_bounds__(GM_THREADS, 2)
gemm_one(const float* __restrict__ A, int lda,
         const float* __restrict__ Bw, int ldb,
         const float* __restrict__ bias,
         float* __restrict__ C, int ldc,
         const int* __restrict__ tok,
         int M, int N, int K)
{
    gemm_body<GNST>(A, lda, Bw, ldb, bias, C, ldc, tok, M, N, K,
                    blockIdx.x, blockIdx.y);
}

// ---------------------------------------------------------------------------
// fp32 SGEMM (small hb2 GEMM only)
// ---------------------------------------------------------------------------
__global__ void __launch_bounds__(256)
sgemm_nt(const float* __restrict__ A, int lda,
         const float* __restrict__ Bw, int ldb,
         const float* __restrict__ bias,
         float* __restrict__ C, int ldc,
         int M, int N, int K)
{
    __shared__ __align__(16) float As[8][132];
    __shared__ __align__(16) float Bs[8][128];

    const int tid  = threadIdx.x;
    const int row0 = blockIdx.y * 128;
    const int col0 = blockIdx.x * 128;

    const int li = tid >> 1;
    const int lk = (tid & 1) * 4;

    int ar = row0 + li;
    if (ar >= M) ar = M - 1;
    const float* Ap = A + (size_t)ar * lda + lk;

    int brn = col0 + li;
    const bool bval = (brn < N);
    const float* Bp = Bw + (size_t)(bval ? brn : 0) * ldb + lk;

    const int ty = tid >> 4;
    const int tx = tid & 15;

    unsigned long long acc2[8][4];
#pragma unroll
    for (int r = 0; r < 8; r++)
#pragma unroll
        for (int c = 0; c < 4; c++) acc2[r][c] = 0ull;

    for (int k0 = 0; k0 < K; k0 += 8) {
        float4 av = *(const float4*)(Ap + k0);
        float4 bv = bval ? *(const float4*)(Bp + k0) : make_float4(0.f, 0.f, 0.f, 0.f);

        __syncthreads();
        As[lk + 0][li] = av.x; As[lk + 1][li] = av.y;
        As[lk + 2][li] = av.z; As[lk + 3][li] = av.w;
        Bs[lk + 0][li] = bv.x; Bs[lk + 1][li] = bv.y;
        Bs[lk + 2][li] = bv.z; Bs[lk + 3][li] = bv.w;
        __syncthreads();

#pragma unroll
        for (int kk = 0; kk < 8; kk++) {
            float4 a0 = *(const float4*)&As[kk][ty * 8];
            float4 a1 = *(const float4*)&As[kk][ty * 8 + 4];
            const unsigned long long* bp = (const unsigned long long*)&Bs[kk][tx * 8];
            unsigned long long b0 = bp[0], b1 = bp[1], b2 = bp[2], b3 = bp[3];
            float arr[8] = {a0.x, a0.y, a0.z, a0.w, a1.x, a1.y, a1.z, a1.w};
#pragma unroll
            for (int r = 0; r < 8; r++) {
                unsigned long long ad = f2pack(arr[r], arr[r]);
                ffma2(acc2[r][0], ad, b0);
                ffma2(acc2[r][1], ad, b1);
                ffma2(acc2[r][2], ad, b2);
                ffma2(acc2[r][3], ad, b3);
            }
        }
    }

    const bool fullcol = (col0 + 128 <= N);
#pragma unroll
    for (int r = 0; r < 8; r++) {
        int row = row0 + ty * 8 + r;
        if (row >= M) continue;
        float* Cp = C + (size_t)row * ldc + col0 + tx * 8;
        float v[8];
#pragma unroll
        for (int c = 0; c < 4; c++) f2unpack(acc2[r][c], v[2 * c], v[2 * c + 1]);
        if (fullcol) {
            if (bias) {
#pragma unroll
                for (int c = 0; c < 8; c++) v[c] += bias[col0 + tx * 8 + c];
            }
            *(float4*)(Cp)     = make_float4(v[0], v[1], v[2], v[3]);
            *(float4*)(Cp + 4) = make_float4(v[4], v[5], v[6], v[7]);
        } else {
#pragma unroll
            for (int c = 0; c < 8; c++) {
                int col = col0 + tx * 8 + c;
                if (col < N) Cp[c] = v[c] + (bias ? bias[col] : 0.f);
            }
        }
    }
}

// ---------------------------------------------------------------------------
// GRU scan v12: W in regs + immediate push + LOCAL-GEMV OVERLAP of the
// DSMEM wait. A CTA's own 64 h-columns never transit DSMEM (self-stored
// locally in the prior phase-2), so threads whose k-half contains the local
// window (kh == rank>>1) compute those 32 k-pairs BEFORE the mbarrier wait,
// shrinking the post-wait issue load from 1536 to 1152 warp-instrs.
//
// Smem (bytes):
//   [0,     4224)  h   [2][2 lanes][264] float
//   [4224,  7296)  sgf [2 kh][2 lanes][192] float
//   [7296, 10368)  xs  [2][2][192] float
//   [10368,11904)  xb  [2][192]   float
//   [11904,11920)  mb  [2] mbarrier
// ---------------------------------------------------------------------------
#define SC_H   0
#define SC_SG  4224
#define SC_XS  7296
#define SC_XB  10368
#define SC_MB  11904
#define SC_SMEM 11920

__global__ void __launch_bounds__(SCAN_THREADS, 1) __cluster_dims__(CL, 1, 1)
gru_cluster(const float* __restrict__ xg,
            const float* __restrict__ hb,
            const float* __restrict__ WT,
            const float* __restrict__ bhh,
            float* __restrict__ hfin,
            float* __restrict__ preds,
            float* __restrict__ tail)
{
    float*  hbuf = (float*) (dsmem + SC_H);
    float*  sgf  = (float*) (dsmem + SC_SG);
    float*  xs   = (float*) (dsmem + SC_XS);
    float*  xb   = (float*) (dsmem + SC_XB);

    const int tid  = threadIdx.x;
    const int cid  = blockIdx.x / CL;
    const int rank = (int)my_ctarank();
    const int b0   = cid * LP;
    const int colbase = rank * 64;

    const uint32_t mybase = smem_u32(dsmem);
    uint32_t peerbase[CL];
#pragma unroll
    for (int p = 0; p < CL; p++) peerbase[p] = mapa_u32(mybase, p);

    if (tid == 0) {
        MBAR_INIT(mybase + SC_MB, 1);
        MBAR_INIT(mybase + SC_MB + 8, 1);
    }

    const int kh  = tid / 192;
    const int gc  = tid - kh * 192;
    const int g   = gc >> 6;
    const int col = gc & 63;
    const int k0  = kh * 128;
    const int woff = g * NHID + colbase + col;

    // does this thread's k-half contain the CTA-local h window?
    const bool prek = (kh == (rank >> 1));
    const int  P0   = (rank & 1) * 32;      // local window pair offset

    unsigned long long w2u[64];
#pragma unroll
    for (int j = 0; j < 64; j++) {
        float lo = WT[(size_t)(k0 + 2 * j)     * G3 + woff];
        float hi = WT[(size_t)(k0 + 2 * j + 1) * G3 + woff];
        w2u[j] = f2pack(lo, hi);
    }

    for (int i = tid; i < (2 * HB) / 4; i += SCAN_THREADS)
        ((float4*)hbuf)[i] = make_float4(0.f, 0.f, 0.f, 0.f);
    for (int i = tid; i < LP * 192; i += SCAN_THREADS) {
        int b = i / 192, j = i - 192 * b;
        int gg = j >> 6, cc = j & 63;
        xb[i] = hb ? hb[(size_t)(b0 + b) * G3 + gg * NHID + colbase + cc] : 0.f;
    }

    unsigned long long bias2 = 0ull;
    if (kh == 0) bias2 = f2pack(bhh[woff], 0.f);

    const int pb = tid / 48;
    const int pj = tid - 48 * pb;
    const int pg = pj >> 4, pf = pj & 15;
    const bool pfv = (tid < 96);
    const float* xgp = pfv
        ? xg + (size_t)(b0 + pb) * G3 + pg * NHID + colbase + pf * 4 : xg;
    float* xss = xs + (pfv ? pb * 192 + pg * 64 + pf * 4 : 0);

    float4 v = pfv ? *(const float4*)(xgp) : make_float4(0.f, 0.f, 0.f, 0.f);
    if (pfv) {
        *(float4*)(xss) = v;
        v = *(const float4*)(xgp + (size_t)BB * G3);
    }

    __syncthreads();
    asm volatile("barrier.cluster.arrive.aligned;" ::: "memory");
    asm volatile("barrier.cluster.wait.aligned;"   ::: "memory");

    int ph[2] = {0, 0};

    for (int t = 0; t < TT; t++) {
        const int cur = t & 1;
        const int nxt = cur ^ 1;

        const float* hc = hbuf + cur * HB;
        const unsigned long long* h0p =
            (const unsigned long long*)(hc + k0);
        const unsigned long long* h1p =
            (const unsigned long long*)(hc + LSTRIDE + k0);
        unsigned long long a0 = bias2, a1 = bias2;

        // ---- pre-wait GEMV on the CTA-local h window (no DSMEM dep) ----
        if (prek) {
#pragma unroll
            for (int jj = 0; jj < 16; jj++) {
                int j = P0 / 2 + jj;   // pairs P0..P0+31 as 16 ulonglong2 steps
                ulonglong2 h0 = *(const ulonglong2*)(h0p + 2 * j);
                ulonglong2 h1 = *(const ulonglong2*)(h1p + 2 * j);
                ffma2(a0, w2u[2 * j],     h0.x);
                ffma2(a0, w2u[2 * j + 1], h0.y);
                ffma2(a1, w2u[2 * j],     h1.x);
                ffma2(a1, w2u[2 * j + 1], h1.y);
            }
        }

        if (t > 0) {
            MBAR_WAIT_CL(mybase + SC_MB + cur * 8, ph[cur]);
            ph[cur] ^= 1;
        }
        if (tid == 0 && t < TT - 1)
            MBAR_EXPECT(mybase + SC_MB + nxt * 8, (CL - 1) * 512);

        // ---- post-wait GEMV on the remaining k-pairs ----
        if (prek) {
            const int Q0 = (32 - P0) / 2;   // other half, 16 ulonglong2 steps
#pragma unroll
            for (int jj = 0; jj < 16; jj++) {
                int j = Q0 + jj;
                ulonglong2 h0 = *(const ulonglong2*)(h0p + 2 * j);
                ulonglong2 h1 = *(const ulonglong2*)(h1p + 2 * j);
                ffma2(a0, w2u[2 * j],     h0.x);
                ffma2(a0, w2u[2 * j + 1], h0.y);
                ffma2(a1, w2u[2 * j],     h1.x);
                ffma2(a1, w2u[2 * j + 1], h1.y);
            }
        } else {
#pragma unroll
            for (int j = 0; j < 32; j++) {
                ulonglong2 h0 = *(const ulonglong2*)(h0p + 2 * j);
                ulonglong2 h1 = *(const ulonglong2*)(h1p + 2 * j);
                ffma2(a0, w2u[2 * j],     h0.x);
                ffma2(a0, w2u[2 * j + 1], h0.y);
                ffma2(a1, w2u[2 * j],     h1.x);
                ffma2(a1, w2u[2 * j + 1], h1.y);
            }
        }
        {
            float e, o;
            f2unpack(a0, e, o);
            sgf[kh * 384 + gc] = e + o;
            f2unpack(a1, e, o);
            sgf[kh * 384 + 192 + gc] = e + o;
        }
        __syncthreads();

        // ---- phase 2: gates + update + immediate dataflow push ----
        if (tid < LP * 64) {
            int tb = tid >> 6;
            int c  = tid & 63;
            const float* xr  = xs + cur * 384 + tb * 192;
            const float* xbr = xb + tb * 192;
            int base = tb * 192 + c;
            float hgr = sgf[base]        + sgf[384 + base];
            float hgz = sgf[base + 64]   + sgf[384 + base + 64];
            float hgn = sgf[base + 128]  + sgf[384 + base + 128];
            float gr = xr[c]       + xbr[c];
            float gz = xr[64 + c]  + xbr[64 + c];
            float gn = xr[128 + c] + xbr[128 + c];
            float ho = hc[tb * LSTRIDE + colbase + c];
            float rr = 1.f / (1.f + __expf(-(gr + hgr)));
            float zz = 1.f / (1.f + __expf(-(gz + hgz)));
            float nn = tanhf(gn + rr * hgn);
            float hn = (1.f - zz) * nn + zz * ho;
            if (preds)
                preds[(size_t)(t * BB + b0 + tb) * NHID + colbase + c] =
                    to_tf32f(hn);
            if (t == TT - 1) {
                if (hfin) hfin[(size_t)(b0 + tb) * NHID + colbase + c] = hn;
                if (tail) tail[(size_t)(b0 + tb) * NHID + colbase + c] = hn;
            } else {
                hbuf[nxt * HB + tb * LSTRIDE + colbase + c] = hn;  // self local
                uint32_t off  = SC_H +
                    (uint32_t)(nxt * HB + tb * LSTRIDE + colbase + c) * 4;
                uint32_t moff = SC_MB + (uint32_t)nxt * 8;
#pragma unroll
                for (int pr = 0; pr < CL - 1; pr++) {
                    int peer = (rank + 1 + pr) & (CL - 1);
                    st_async_f32(peerbase[peer] + off,
                                 peerbase[peer] + moff, hn);
                }
            }
        }
        if (t == TT - 1) break;

        if (pfv) {
            *(float4*)(xss + nxt * 384) = v;
            if (t + 2 < TT)
                v = *(const float4*)(xgp + (size_t)(t + 2) * BB * G3);
        }
        __syncthreads();  // hbuf[nxt] self-stores + xs[nxt] visible next step
    }

    asm volatile("barrier.cluster.arrive.aligned;" ::: "memory");
    asm volatile("barrier.cluster.wait.aligned;"   ::: "memory");
}

// ---------------------------------------------------------------------------
// Launcher
// ---------------------------------------------------------------------------
extern "C" void kernel_launch(void* const* d_in, const int* in_sizes, int n_in,
                              void* d_out, int out_size)
{
    const int*   tokens = (const int*)  d_in[0];
    const float* E      = (const float*)d_in[1];
    const float* Wih1   = (const float*)d_in[2];
    const float* Whh1   = (const float*)d_in[3];
    const float* bih1   = (const float*)d_in[4];
    const float* bhh1   = (const float*)d_in[5];
    const float* Wih2   = (const float*)d_in[6];
    const float* Whh2   = (const float*)d_in[7];
    const float* bih2   = (const float*)d_in[8];
    const float* bhh2   = (const float*)d_in[9];
    // d_in[10..14] dead (attention context == h1 exactly)
    const float* Wd     = (const float*)d_in[15];
    const float* bd     = (const float*)d_in[16];
    float* out = (float*)d_out;

    float *xg1, *xg2, *hb2, *h1, *preds, *WT1, *WT2, *Et, *Wdt, *W1t, *W2t;
    cudaGetSymbolAddress((void**)&xg1,   g_xg1);
    cudaGetSymbolAddress((void**)&xg2,   g_xg2);
    cudaGetSymbolAddress((void**)&hb2,   g_hb2);
    cudaGetSymbolAddress((void**)&h1,    g_h1);
    cudaGetSymbolAddress((void**)&preds, g_preds);
    cudaGetSymbolAddress((void**)&WT1,   g_WT1);
    cudaGetSymbolAddress((void**)&WT2,   g_WT2);
    cudaGetSymbolAddress((void**)&Et,    g_Et);
    cudaGetSymbolAddress((void**)&Wdt,   g_Wdt);
    cudaGetSymbolAddress((void**)&W1t,   g_W1t);
    cudaGetSymbolAddress((void**)&W2t,   g_W2t);

    cudaFuncSetAttribute(gru_cluster, cudaFuncAttributeMaxDynamicSharedMemorySize,
                         SC_SMEM);
    cudaFuncSetAttribute(gemm_one, cudaFuncAttributeMaxDynamicSharedMemorySize,
                         GM_SMEM);

    float* tail = nullptr;
    if (out_size >= MM * NVOC + BB * NHID) tail = out + (size_t)MM * NVOC;

    prepass_all<<<2048, 256>>>(E, Et, Wd, Wdt, Wih1, W1t, Wih2 + NHID, W2t);
    transpose_k2<<<dim3(24, 8, 2), dim3(32, 8)>>>(Whh1, WT1, Whh2, WT2);

    gemm_one<<<dim3(6, 64), GM_THREADS, GM_SMEM>>>(
        Et, NIN, W1t, NIN, bih1, xg1, G3, tokens, MM, G3, NIN);
    gemm_one<<<dim3(6, 64), GM_THREADS, GM_SMEM>>>(
        Et, NIN, W2t, NIN, nullptr, xg2, G3, tokens, MM, G3, NIN);

    gru_cluster<<<NCLUST * CL, SCAN_THREADS, SC_SMEM>>>(
        xg1, nullptr, WT1, bhh1, h1, nullptr, tail);

    sgemm_nt<<<dim3(6, 1), 256>>>(h1, NHID, Wih2, NHID + NIN, bih2,
                                  hb2, G3, BB, G3, NHID);

    gru_cluster<<<NCLUST * CL, SCAN_THREADS, SC_SMEM>>>(
        xg2, hb2, WT2, bhh2, nullptr, preds, nullptr);

    gemm_one<<<dim3(79, 64), GM_THREADS, GM_SMEM>>>(
        preds, NHID, Wdt, NHID, bd, out, NVOC, nullptr, MM, NVOC, NHID);
}

// round 17
// speedup vs baseline: 1.3835x; 1.3835x over previous
#include <cuda_runtime.h>
#include <cuda_bf16.h>
#include <cstdint>

// ---------------------------------------------------------------------------
// Problem constants
// ---------------------------------------------------------------------------
#define NVOC 10000
#define NIN  1024
#define NHID 256
#define G3   768
#define TT   128
#define BB   64
#define MM   (TT*BB)

#define CL 4                  // CTAs per cluster
#define LP 2                  // batch lanes per cluster
#define NCLUST (BB/LP)        // 32 clusters
#define SCAN_THREADS 384
#define LSTRIDE 264           // padded lane stride (floats)
#define HB (LP*LSTRIDE)

extern __shared__ char dsmem[];

// ---------------------------------------------------------------------------
// Device scratch
// ---------------------------------------------------------------------------
__device__ float g_xg1  [MM * G3];
__device__ float g_xg2  [MM * G3];
__device__ float g_hb2  [BB * G3];
__device__ float g_h1   [BB * NHID];
__device__ float g_preds[MM * NHID];
__device__ float g_WT1  [NHID * G3];
__device__ float g_WT2  [NHID * G3];
__device__ float g_Et  [NVOC * NIN];
__device__ float g_Wdt [NVOC * NHID];
__device__ float g_W1t [G3 * NIN];
__device__ float g_W2t [G3 * NIN];

// ---------------------------------------------------------------------------
// Helpers
// ---------------------------------------------------------------------------
__device__ __forceinline__ uint32_t smem_u32(const void* p) {
    uint32_t a;
    asm("{ .reg .u64 t; cvta.to.shared.u64 t, %1; cvt.u32.u64 %0, t; }"
        : "=r"(a) : "l"(p));
    return a;
}
__device__ __forceinline__ float to_tf32f(float x) {
    float y;
    asm("cvt.rna.tf32.f32 %0, %1;" : "=f"(y) : "f"(x));
    return y;
}
__device__ __forceinline__ unsigned long long f2pack(float lo, float hi) {
    unsigned long long v;
    asm("mov.b64 %0, {%1, %2};" : "=l"(v) : "f"(lo), "f"(hi));
    return v;
}
__device__ __forceinline__ void f2unpack(unsigned long long v, float& lo, float& hi) {
    asm("mov.b64 {%0, %1}, %2;" : "=f"(lo), "=f"(hi) : "l"(v));
}
__device__ __forceinline__ void ffma2(unsigned long long& d, unsigned long long a,
                                      unsigned long long b) {
    asm("fma.rn.f32x2 %0, %1, %2, %3;" : "=l"(d) : "l"(a), "l"(b), "l"(d));
}
__device__ __forceinline__ void mma_tf32(float* d, uint32_t a0, uint32_t a1,
                                         uint32_t a2, uint32_t a3,
                                         uint32_t b0, uint32_t b1) {
    asm volatile(
        "mma.sync.aligned.m16n8k8.row.col.f32.tf32.tf32.f32 "
        "{%0,%1,%2,%3}, {%4,%5,%6,%7}, {%8,%9}, {%0,%1,%2,%3};"
        : "+f"(d[0]), "+f"(d[1]), "+f"(d[2]), "+f"(d[3])
        : "r"(a0), "r"(a1), "r"(a2), "r"(a3), "r"(b0), "r"(b1));
}
__device__ __forceinline__ uint32_t my_ctarank() {
    uint32_t r;
    asm("mov.u32 %0, %%cluster_ctarank;" : "=r"(r));
    return r;
}
__device__ __forceinline__ uint32_t mapa_u32(uint32_t laddr, int p) {
    uint32_t ra;
    asm volatile("mapa.shared::cluster.u32 %0, %1, %2;"
                 : "=r"(ra) : "r"(laddr), "r"(p));
    return ra;
}
__device__ __forceinline__ void st_async_f32(uint32_t raddr, uint32_t rmbar,
                                             float v) {
    asm volatile(
        "st.async.shared::cluster.mbarrier::complete_tx::bytes.b32 [%0], %1, [%2];"
        :: "r"(raddr), "r"(__float_as_uint(v)), "r"(rmbar) : "memory");
}
__device__ __forceinline__ void cp_async16(uint32_t dst, const void* src) {
    asm volatile("cp.async.cg.shared.global [%0], [%1], 16;"
                 :: "r"(dst), "l"(src) : "memory");
}
#define CP_COMMIT() asm volatile("cp.async.commit_group;" ::: "memory")

#define MBAR_INIT(a, n) \
    asm volatile("mbarrier.init.shared.b64 [%0], %1;" :: "r"(a), "r"(n) : "memory")
#define MBAR_EXPECT(a, tx) \
    asm volatile("mbarrier.arrive.expect_tx.shared.b64 _, [%0], %1;" \
                 :: "r"(a), "r"(tx) : "memory")
#define MBAR_WAIT_CL(a, ph) do {                                                \
    uint32_t _m = (a), _p = (ph), _d;                                           \
    asm volatile("{ .reg .pred p; "                                             \
        "mbarrier.try_wait.parity.acquire.cluster.shared::cta.b64 p, [%1], %2;" \
        " selp.b32 %0, 1, 0, p; }" : "=r"(_d) : "r"(_m), "r"(_p) : "memory");   \
    if (!_d) {                                                                  \
        asm volatile("{ .reg .pred P1; WL%=:"                                   \
            " mbarrier.try_wait.parity.acquire.cluster.shared::cta.b64 P1, [%0], %1, 0x989680;" \
            " @P1 bra.uni WD%=; bra.uni WL%=; WD%=: }"                          \
            :: "r"(_m), "r"(_p) : "memory");                                    \
    } } while (0)

// ---------------------------------------------------------------------------
// Fused tf32 pre-rounding prepass
// ---------------------------------------------------------------------------
#define NE4  (NVOC * NIN / 4)
#define NWD4 (NVOC * NHID / 4)
#define NW14 (G3 * NIN / 4)
#define NW24 (G3 * NIN / 4)

__global__ void prepass_all(const float* __restrict__ E,  float* __restrict__ Et,
                            const float* __restrict__ Wd, float* __restrict__ Wdt,
                            const float* __restrict__ W1, float* __restrict__ W1t,
                            const float* __restrict__ W2, float* __restrict__ W2t)
{
    const int total = NE4 + NWD4 + NW14 + NW24;
    for (int i = blockIdx.x * blockDim.x + threadIdx.x; i < total;
         i += gridDim.x * blockDim.x) {
        const float4* src;
        float4* dst;
        if (i < NE4) {
            src = (const float4*)E + i;
            dst = (float4*)Et + i;
        } else if (i < NE4 + NWD4) {
            int j = i - NE4;
            src = (const float4*)Wd + j;
            dst = (float4*)Wdt + j;
        } else if (i < NE4 + NWD4 + NW14) {
            int j = i - NE4 - NWD4;
            src = (const float4*)W1 + j;
            dst = (float4*)W1t + j;
        } else {
            int j = i - NE4 - NWD4 - NW14;
            int r = j / (NIN / 4), c = j - r * (NIN / 4);
            src = (const float4*)(W2 + (size_t)r * (NHID + NIN) + c * 4);
            dst = (float4*)(W2t + (size_t)r * NIN + c * 4);
        }
        float4 v = *src;
        v.x = to_tf32f(v.x); v.y = to_tf32f(v.y);
        v.z = to_tf32f(v.z); v.w = to_tf32f(v.w);
        *dst = v;
    }
}

// ---------------------------------------------------------------------------
__global__ void transpose_k2(const float* __restrict__ in0, float* __restrict__ out0,
                             const float* __restrict__ in1, float* __restrict__ out1)
{
    __shared__ float tile[32][33];
    const float* in  = blockIdx.z ? in1  : in0;
    float*       out = blockIdx.z ? out1 : out0;
    int r0 = blockIdx.x * 32;
    int c0 = blockIdx.y * 32;
    for (int i = threadIdx.y; i < 32; i += 8)
        tile[i][threadIdx.x] = in[(r0 + i) * NHID + (c0 + threadIdx.x)];
    __syncthreads();
    for (int i = threadIdx.y; i < 32; i += 8)
        out[(c0 + i) * G3 + (r0 + threadIdx.x)] = tile[threadIdx.x][i];
}

// ---------------------------------------------------------------------------
// tf32 mma.sync GEMM body (operands pre-rounded).
// ---------------------------------------------------------------------------
#define GM_THREADS 256
#define GNST 3
#define GM_SMEM (GNST * 32768)

template<int NST>
__device__ __forceinline__ void
gemm_body(const float* __restrict__ A, int lda,
          const float* __restrict__ Bw, int ldb,
          const float* __restrict__ bias,
          float* __restrict__ C, int ldc,
          const int* __restrict__ tok,
          int M, int N, int K, int bx, int by)
{
    float* smem = (float*)dsmem;
    const uint32_t sbase = smem_u32(dsmem);

    const int tid  = threadIdx.x;
    const int wid  = tid >> 5, lane = tid & 31;
    const int wm   = wid >> 1;
    const int wn   = wid & 1;
    const int gid  = lane >> 2;
    const int tig  = lane & 3;
    const int row0 = by * 128, col0 = bx * 128;

    const int sr = tid >> 3;
    const int sc = (tid & 7) * 4;
    const float* Aptr[4];
    const float* Bptr[4];
#pragma unroll
    for (int ps = 0; ps < 4; ps++) {
        int ar = row0 + sr + ps * 32;
        if (ar >= M) ar = M - 1;
        if (tok) ar = tok[ar];
        Aptr[ps] = A + (size_t)ar * lda + sc;
        int br = col0 + sr + ps * 32;
        if (br >= N) br = N - 1;
        Bptr[ps] = Bw + (size_t)br * ldb + sc;
    }
    uint32_t stOff[4];
#pragma unroll
    for (int ps = 0; ps < 4; ps++) {
        int r = sr + ps * 32;
        stOff[ps] = (r * 32 + 4 * ((sc >> 2) ^ (r & 7))) * 4;
    }

    const int NC = K >> 5;

    auto issue = [&](int idx) {
        uint32_t ab = sbase + (uint32_t)(idx % NST) * 32768u;
        const int co = idx * 32;
#pragma unroll
        for (int ps = 0; ps < 4; ps++) {
            cp_async16(ab + stOff[ps], Aptr[ps] + co);
            cp_async16(ab + 16384u + stOff[ps], Bptr[ps] + co);
        }
        CP_COMMIT();
    };

#pragma unroll
    for (int s = 0; s < NST - 1; s++) issue(s);

    float acc[2][8][4];
#pragma unroll
    for (int mt = 0; mt < 2; mt++)
#pragma unroll
        for (int nt = 0; nt < 8; nt++)
#pragma unroll
            for (int j = 0; j < 4; j++) acc[mt][nt][j] = 0.f;

    for (int i = 0; i < NC; i++) {
        asm volatile("cp.async.wait_group %0;" :: "n"(NST - 2) : "memory");
        __syncthreads();

        const uint32_t* Au = (const uint32_t*)(smem + (size_t)(i % NST) * 8192);
        const uint32_t* Bu = Au + 4096;

#pragma unroll
        for (int kk = 0; kk < 4; kk++) {
            const int s0 = 4 * (((kk * 2)    ) ^ gid);
            const int s1 = 4 * (((kk * 2) + 1) ^ gid);
            uint32_t af[2][4];
#pragma unroll
            for (int mt = 0; mt < 2; mt++) {
                int rA = wm * 32 + mt * 16 + gid;
                af[mt][0] = Au[rA * 32 + tig + s0];
                af[mt][1] = Au[(rA + 8) * 32 + tig + s0];
                af[mt][2] = Au[rA * 32 + tig + s1];
                af[mt][3] = Au[(rA + 8) * 32 + tig + s1];
            }
            uint32_t bf[8][2];
#pragma unroll
            for (int nt = 0; nt < 8; nt++) {
                int rB = wn * 64 + nt * 8 + gid;
                bf[nt][0] = Bu[rB * 32 + tig + s0];
                bf[nt][1] = Bu[rB * 32 + tig + s1];
            }
#pragma unroll
            for (int mt = 0; mt < 2; mt++)
#pragma unroll
                for (int nt = 0; nt < 8; nt++)
                    mma_tf32(acc[mt][nt], af[mt][0], af[mt][1], af[mt][2],
                             af[mt][3], bf[nt][0], bf[nt][1]);
        }

        if (i + NST - 1 < NC) issue(i + NST - 1);
        else                  CP_COMMIT();
    }

#pragma unroll
    for (int mt = 0; mt < 2; mt++) {
        int row = row0 + wm * 32 + mt * 16 + gid;
        if (row >= M) continue;
#pragma unroll
        for (int nt = 0; nt < 8; nt++) {
            int col = col0 + wn * 64 + nt * 8 + tig * 2;
            if (col >= N) continue;
            float b0v = bias ? bias[col] : 0.f;
            float* p0 = C + (size_t)row * ldc + col;
            float* p1 = C + (size_t)(row + 8) * ldc + col;
            if (col + 1 < N) {
                float b1v = bias ? bias[col + 1] : 0.f;
                *(float2*)p0 = make_float2(acc[mt][nt][0] + b0v,
                                           acc[mt][nt][1] + b1v);
                if (row + 8 < M)
                    *(float2*)p1 = make_float2(acc[mt][nt][2] + b0v,
                                               acc[mt][nt][3] + b1v);
            } else {
                p0[0] = acc[mt][nt][0] + b0v;
                if (row + 8 < M) p1[0] = acc[mt][nt][2] + b0v;
            }
        }
    }
}

__global__ void __launch_bounds__(GM_THREADS, 2)
gemm_one(const float* __restrict__ A, int lda,
         const float* __restrict__ Bw, int ldb,
         const float* __restrict__ bias,
         float* __restrict__ C, int ldc,
         const int* __restrict__ tok,
         int M, int N, int K)
{
    gemm_body<GNST>(A, lda, Bw, ldb, bias, C, ldc, tok, M, N, K,
                    blockIdx.x, blockIdx.y);
}

// ---------------------------------------------------------------------------
// fp32 SGEMM (small hb2 GEMM only)
// ---------------------------------------------------------------------------
__global__ void __launch_bounds__(256)
sgemm_nt(const float* __restrict__ A, int lda,
         const float* __restrict__ Bw, int ldb,
         const float* __restrict__ bias,
         float* __restrict__ C, int ldc,
         int M, int N, int K)
{
    __shared__ __align__(16) float As[8][132];
    __shared__ __align__(16) float Bs[8][128];

    const int tid  = threadIdx.x;
    const int row0 = blockIdx.y * 128;
    const int col0 = blockIdx.x * 128;

    const int li = tid >> 1;
    const int lk = (tid & 1) * 4;

    int ar = row0 + li;
    if (ar >= M) ar = M - 1;
    const float* Ap = A + (size_t)ar * lda + lk;

    int brn = col0 + li;
    const bool bval = (brn < N);
    const float* Bp = Bw + (size_t)(bval ? brn : 0) * ldb + lk;

    const int ty = tid >> 4;
    const int tx = tid & 15;

    unsigned long long acc2[8][4];
#pragma unroll
    for (int r = 0; r < 8; r++)
#pragma unroll
        for (int c = 0; c < 4; c++) acc2[r][c] = 0ull;

    for (int k0 = 0; k0 < K; k0 += 8) {
        float4 av = *(const float4*)(Ap + k0);
        float4 bv = bval ? *(const float4*)(Bp + k0) : make_float4(0.f, 0.f, 0.f, 0.f);

        __syncthreads();
        As[lk + 0][li] = av.x; As[lk + 1][li] = av.y;
        As[lk + 2][li] = av.z; As[lk + 3][li] = av.w;
        Bs[lk + 0][li] = bv.x; Bs[lk + 1][li] = bv.y;
        Bs[lk + 2][li] = bv.z; Bs[lk + 3][li] = bv.w;
        __syncthreads();

#pragma unroll
        for (int kk = 0; kk < 8; kk++) {
            float4 a0 = *(const float4*)&As[kk][ty * 8];
            float4 a1 = *(const float4*)&As[kk][ty * 8 + 4];
            const unsigned long long* bp = (const unsigned long long*)&Bs[kk][tx * 8];
            unsigned long long b0 = bp[0], b1 = bp[1], b2 = bp[2], b3 = bp[3];
            float arr[8] = {a0.x, a0.y, a0.z, a0.w, a1.x, a1.y, a1.z, a1.w};
#pragma unroll
            for (int r = 0; r < 8; r++) {
                unsigned long long ad = f2pack(arr[r], arr[r]);
                ffma2(acc2[r][0], ad, b0);
                ffma2(acc2[r][1], ad, b1);
                ffma2(acc2[r][2], ad, b2);
                ffma2(acc2[r][3], ad, b3);
            }
        }
    }

    const bool fullcol = (col0 + 128 <= N);
#pragma unroll
    for (int r = 0; r < 8; r++) {
        int row = row0 + ty * 8 + r;
        if (row >= M) continue;
        float* Cp = C + (size_t)row * ldc + col0 + tx * 8;
        float v[8];
#pragma unroll
        for (int c = 0; c < 4; c++) f2unpack(acc2[r][c], v[2 * c], v[2 * c + 1]);
        if (fullcol) {
            if (bias) {
#pragma unroll
                for (int c = 0; c < 8; c++) v[c] += bias[col0 + tx * 8 + c];
            }
            *(float4*)(Cp)     = make_float4(v[0], v[1], v[2], v[3]);
            *(float4*)(Cp + 4) = make_float4(v[4], v[5], v[6], v[7]);
        } else {
#pragma unroll
            for (int c = 0; c < 8; c++) {
                int col = col0 + tx * 8 + c;
                if (col < N) Cp[c] = v[c] + (bias ? bias[col] : 0.f);
            }
        }
    }
}

// ---------------------------------------------------------------------------
// GRU scan v11 (R15 winner): W in registers + immediate per-thread dataflow
// push. Uniform (non-divergent) fully-unrolled GEMV; mbarrier wait kept
// OUTSIDE any live accumulator region (the R16 wait-overlap split regressed
// 300us by pinning registers across the poll loop — do not reintroduce).
//
// Smem (bytes):
//   [0,     4224)  h   [2][2 lanes][264] float
//   [4224,  7296)  sgf [2 kh][2 lanes][192] float
//   [7296, 10368)  xs  [2][2][192] float
//   [10368,11904)  xb  [2][192]   float
//   [11904,11920)  mb  [2] mbarrier
// ---------------------------------------------------------------------------
#define SC_H   0
#define SC_SG  4224
#define SC_XS  7296
#define SC_XB  10368
#define SC_MB  11904
#define SC_SMEM 11920

__global__ void __launch_bounds__(SCAN_THREADS, 1) __cluster_dims__(CL, 1, 1)
gru_cluster(const float* __restrict__ xg,
            const float* __restrict__ hb,
            const float* __restrict__ WT,
            const float* __restrict__ bhh,
            float* __restrict__ hfin,
            float* __restrict__ preds,
            float* __restrict__ tail)
{
    float*  hbuf = (float*) (dsmem + SC_H);
    float*  sgf  = (float*) (dsmem + SC_SG);
    float*  xs   = (float*) (dsmem + SC_XS);
    float*  xb   = (float*) (dsmem + SC_XB);

    const int tid  = threadIdx.x;
    const int cid  = blockIdx.x / CL;
    const int rank = (int)my_ctarank();
    const int b0   = cid * LP;
    const int colbase = rank * 64;

    const uint32_t mybase = smem_u32(dsmem);
    uint32_t peerbase[CL];
#pragma unroll
    for (int p = 0; p < CL; p++) peerbase[p] = mapa_u32(mybase, p);

    if (tid == 0) {
        MBAR_INIT(mybase + SC_MB, 1);
        MBAR_INIT(mybase + SC_MB + 8, 1);
    }

    const int kh  = tid / 192;
    const int gc  = tid - kh * 192;
    const int g   = gc >> 6;
    const int col = gc & 63;
    const int k0  = kh * 128;
    const int woff = g * NHID + colbase + col;

    unsigned long long w2u[64];
#pragma unroll
    for (int j = 0; j < 64; j++) {
        float lo = WT[(size_t)(k0 + 2 * j)     * G3 + woff];
        float hi = WT[(size_t)(k0 + 2 * j + 1) * G3 + woff];
        w2u[j] = f2pack(lo, hi);
    }

    for (int i = tid; i < (2 * HB) / 4; i += SCAN_THREADS)
        ((float4*)hbuf)[i] = make_float4(0.f, 0.f, 0.f, 0.f);
    for (int i = tid; i < LP * 192; i += SCAN_THREADS) {
        int b = i / 192, j = i - 192 * b;
        int gg = j >> 6, cc = j & 63;
        xb[i] = hb ? hb[(size_t)(b0 + b) * G3 + gg * NHID + colbase + cc] : 0.f;
    }

    unsigned long long bias2 = 0ull;
    if (kh == 0) bias2 = f2pack(bhh[woff], 0.f);

    const int pb = tid / 48;
    const int pj = tid - 48 * pb;
    const int pg = pj >> 4, pf = pj & 15;
    const bool pfv = (tid < 96);
    const float* xgp = pfv
        ? xg + (size_t)(b0 + pb) * G3 + pg * NHID + colbase + pf * 4 : xg;
    float* xss = xs + (pfv ? pb * 192 + pg * 64 + pf * 4 : 0);

    float4 v = pfv ? *(const float4*)(xgp) : make_float4(0.f, 0.f, 0.f, 0.f);
    if (pfv) {
        *(float4*)(xss) = v;
        v = *(const float4*)(xgp + (size_t)BB * G3);
    }

    __syncthreads();
    asm volatile("barrier.cluster.arrive.aligned;" ::: "memory");
    asm volatile("barrier.cluster.wait.aligned;"   ::: "memory");

    int ph[2] = {0, 0};

    for (int t = 0; t < TT; t++) {
        const int cur = t & 1;
        const int nxt = cur ^ 1;

        if (t > 0) {
            MBAR_WAIT_CL(mybase + SC_MB + cur * 8, ph[cur]);
            ph[cur] ^= 1;
        }
        if (tid == 0 && t < TT - 1)
            MBAR_EXPECT(mybase + SC_MB + nxt * 8, (CL - 1) * 512);

        // ---- GEMV: W in regs, h k-pairs from smem (warp-broadcast) ----
        const float* hc = hbuf + cur * HB;
        const unsigned long long* h0p =
            (const unsigned long long*)(hc + k0);
        const unsigned long long* h1p =
            (const unsigned long long*)(hc + LSTRIDE + k0);
        unsigned long long a0 = bias2, a1 = bias2;
#pragma unroll
        for (int j = 0; j < 32; j++) {
            ulonglong2 h0 = *(const ulonglong2*)(h0p + 2 * j);
            ulonglong2 h1 = *(const ulonglong2*)(h1p + 2 * j);
            ffma2(a0, w2u[2 * j],     h0.x);
            ffma2(a0, w2u[2 * j + 1], h0.y);
            ffma2(a1, w2u[2 * j],     h1.x);
            ffma2(a1, w2u[2 * j + 1], h1.y);
        }
        {
            float e, o;
            f2unpack(a0, e, o);
            sgf[kh * 384 + gc] = e + o;
            f2unpack(a1, e, o);
            sgf[kh * 384 + 192 + gc] = e + o;
        }
        __syncthreads();

        // ---- phase 2: gates + update + IMMEDIATE dataflow push ----
        if (tid < LP * 64) {
            int tb = tid >> 6;
            int c  = tid & 63;
            const float* xr  = xs + cur * 384 + tb * 192;
            const float* xbr = xb + tb * 192;
            int base = tb * 192 + c;
            float hgr = sgf[base]        + sgf[384 + base];
            float hgz = sgf[base + 64]   + sgf[384 + base + 64];
            float hgn = sgf[base + 128]  + sgf[384 + base + 128];
            float gr = xr[c]       + xbr[c];
            float gz = xr[64 + c]  + xbr[64 + c];
            float gn = xr[128 + c] + xbr[128 + c];
            float ho = hc[tb * LSTRIDE + colbase + c];
            float rr = 1.f / (1.f + __expf(-(gr + hgr)));
            float zz = 1.f / (1.f + __expf(-(gz + hgz)));
            float nn = tanhf(gn + rr * hgn);
            float hn = (1.f - zz) * nn + zz * ho;
            if (preds)
                preds[(size_t)(t * BB + b0 + tb) * NHID + colbase + c] =
                    to_tf32f(hn);
            if (t == TT - 1) {
                if (hfin) hfin[(size_t)(b0 + tb) * NHID + colbase + c] = hn;
                if (tail) tail[(size_t)(b0 + tb) * NHID + colbase + c] = hn;
            } else {
                hbuf[nxt * HB + tb * LSTRIDE + colbase + c] = hn;  // self local
                uint32_t off  = SC_H +
                    (uint32_t)(nxt * HB + tb * LSTRIDE + colbase + c) * 4;
                uint32_t moff = SC_MB + (uint32_t)nxt * 8;
#pragma unroll
                for (int pr = 0; pr < CL - 1; pr++) {
                    int peer = (rank + 1 + pr) & (CL - 1);
                    st_async_f32(peerbase[peer] + off,
                                 peerbase[peer] + moff, hn);
                }
            }
        }
        if (t == TT - 1) break;

        // stage next step's input gates, prefetch t+2
        if (pfv) {
            *(float4*)(xss + nxt * 384) = v;
            if (t + 2 < TT)
                v = *(const float4*)(xgp + (size_t)(t + 2) * BB * G3);
        }
        __syncthreads();  // hbuf[nxt] self-stores + xs[nxt] visible next step
    }

    asm volatile("barrier.cluster.arrive.aligned;" ::: "memory");
    asm volatile("barrier.cluster.wait.aligned;"   ::: "memory");
}

// ---------------------------------------------------------------------------
// Launcher
// ---------------------------------------------------------------------------
extern "C" void kernel_launch(void* const* d_in, const int* in_sizes, int n_in,
                              void* d_out, int out_size)
{
    const int*   tokens = (const int*)  d_in[0];
    const float* E      = (const float*)d_in[1];
    const float* Wih1   = (const float*)d_in[2];
    const float* Whh1   = (const float*)d_in[3];
    const float* bih1   = (const float*)d_in[4];
    const float* bhh1   = (const float*)d_in[5];
    const float* Wih2   = (const float*)d_in[6];
    const float* Whh2   = (const float*)d_in[7];
    const float* bih2   = (const float*)d_in[8];
    const float* bhh2   = (const float*)d_in[9];
    // d_in[10..14] dead (attention context == h1 exactly)
    const float* Wd     = (const float*)d_in[15];
    const float* bd     = (const float*)d_in[16];
    float* out = (float*)d_out;

    float *xg1, *xg2, *hb2, *h1, *preds, *WT1, *WT2, *Et, *Wdt, *W1t, *W2t;
    cudaGetSymbolAddress((void**)&xg1,   g_xg1);
    cudaGetSymbolAddress((void**)&xg2,   g_xg2);
    cudaGetSymbolAddress((void**)&hb2,   g_hb2);
    cudaGetSymbolAddress((void**)&h1,    g_h1);
    cudaGetSymbolAddress((void**)&preds, g_preds);
    cudaGetSymbolAddress((void**)&WT1,   g_WT1);
    cudaGetSymbolAddress((void**)&WT2,   g_WT2);
    cudaGetSymbolAddress((void**)&Et,    g_Et);
    cudaGetSymbolAddress((void**)&Wdt,   g_Wdt);
    cudaGetSymbolAddress((void**)&W1t,   g_W1t);
    cudaGetSymbolAddress((void**)&W2t,   g_W2t);

    cudaFuncSetAttribute(gru_cluster, cudaFuncAttributeMaxDynamicSharedMemorySize,
                         SC_SMEM);
    cudaFuncSetAttribute(gemm_one, cudaFuncAttributeMaxDynamicSharedMemorySize,
                         GM_SMEM);

    float* tail = nullptr;
    if (out_size >= MM * NVOC + BB * NHID) tail = out + (size_t)MM * NVOC;

    prepass_all<<<2048, 256>>>(E, Et, Wd, Wdt, Wih1, W1t, Wih2 + NHID, W2t);
    transpose_k2<<<dim3(24, 8, 2), dim3(32, 8)>>>(Whh1, WT1, Whh2, WT2);

    gemm_one<<<dim3(6, 64), GM_THREADS, GM_SMEM>>>(
        Et, NIN, W1t, NIN, bih1, xg1, G3, tokens, MM, G3, NIN);
    gemm_one<<<dim3(6, 64), GM_THREADS, GM_SMEM>>>(
        Et, NIN, W2t, NIN, nullptr, xg2, G3, tokens, MM, G3, NIN);

    gru_cluster<<<NCLUST * CL, SCAN_THREADS, SC_SMEM>>>(
        xg1, nullptr, WT1, bhh1, h1, nullptr, tail);

    sgemm_nt<<<dim3(6, 1), 256>>>(h1, NHID, Wih2, NHID + NIN, bih2,
                                  hb2, G3, BB, G3, NHID);

    gru_cluster<<<NCLUST * CL, SCAN_THREADS, SC_SMEM>>>(
        xg2, hb2, WT2, bhh2, nullptr, preds, nullptr);

    gemm_one<<<dim3(79, 64), GM_THREADS, GM_SMEM>>>(
        preds, NHID, Wdt, NHID, bd, out, NVOC, nullptr, MM, NVOC, NHID);
}